// round 4
// baseline (speedup 1.0000x reference)
#include <cuda_runtime.h>

// Problem constants (from reference): V=100000, C0=16, C1=16, E=1600000
#define VMAX 100000

// Scratch: [deg | mag | agg1 | agg2], each VMAX floats
__device__ float g_scratch[4 * VMAX];

__global__ __launch_bounds__(256) void zero_kernel(int n) {
    int i = blockIdx.x * blockDim.x + threadIdx.x;
    if (i < n) g_scratch[i] = 0.0f;
}

// Per-edge message computation + scatter via atomics.
// Shared weight layout: [0:16) w_n00, [16:48) w_n10 (k*2+c), [48:80) w_n01 (k*2+c), [80:144) w_n11 (k*4+c)
__global__ __launch_bounds__(256) void edge_kernel(
    const float* __restrict__ x,
    const int* __restrict__ ei,             // [2, E] int32: src then dst
    const float* __restrict__ angles,
    const float* __restrict__ transporters,
    const float* __restrict__ w_n00,
    const float* __restrict__ w_n10,
    const float* __restrict__ w_n01,
    const float* __restrict__ w_n11,
    int E)
{
    __shared__ float sw[144];
    int t = threadIdx.x;
    if (t < 16)              sw[t] = w_n00[t];
    else if (t < 48)         sw[t] = w_n10[t - 16];
    else if (t < 80)         sw[t] = w_n01[t - 48];
    else if (t < 144)        sw[t] = w_n11[t - 80];
    __syncthreads();

    int e = blockIdx.x * blockDim.x + t;
    if (e >= E) return;

    int s = ei[e];
    int d = ei[E + e];

    float sg, cg; __sincosf(transporters[e], &sg, &cg);
    float st, ct; __sincosf(angles[e],       &st, &ct);
    float c2t = ct * ct - st * st;
    float s2t = 2.0f * st * ct;

    const float4* xr = (const float4*)(x + (long long)s * 48);

    // x0 dot products: m0x = x0.w_n00, sa = x0.w_n01[:,0], sb = x0.w_n01[:,1]
    float m0x = 0.f, sa = 0.f, sb = 0.f;
#pragma unroll
    for (int i = 0; i < 4; i++) {
        float4 v = __ldg(&xr[i]);
        float vv[4] = {v.x, v.y, v.z, v.w};
#pragma unroll
        for (int j = 0; j < 4; j++) {
            int k = i * 4 + j;
            m0x = fmaf(vv[j], sw[k],              m0x);
            sa  = fmaf(vv[j], sw[48 + 2 * k],     sa);
            sb  = fmaf(vv[j], sw[48 + 2 * k + 1], sb);
        }
    }

    // x1 part: u1/u2 rotation + 12 dot products, streamed
    float A = 0.f, B = 0.f, Cc = 0.f, Dd = 0.f;
    float Up = 0.f, Uq = 0.f, Ur = 0.f, Us = 0.f;
    float Vp = 0.f, Vq = 0.f, Vr = 0.f, Vs = 0.f;
#pragma unroll
    for (int i = 0; i < 8; i++) {
        float4 v = __ldg(&xr[4 + i]);
#pragma unroll
        for (int h = 0; h < 2; h++) {
            int k   = 2 * i + h;
            float a1 = (h == 0) ? v.x : v.z;  // x1[k,0]
            float b1 = (h == 0) ? v.y : v.w;  // x1[k,1]
            float u1 = cg * a1 - sg * b1;
            float u2 = sg * a1 + cg * b1;
            float wa = sw[16 + 2 * k], wb = sw[16 + 2 * k + 1];
            A  = fmaf(u1, wa, A);  B  = fmaf(u2, wa, B);
            Cc = fmaf(u1, wb, Cc); Dd = fmaf(u2, wb, Dd);
            float p = sw[80 + 4 * k], q = sw[80 + 4 * k + 1];
            float r = sw[80 + 4 * k + 2], ss = sw[80 + 4 * k + 3];
            Up = fmaf(u1, p, Up); Uq = fmaf(u1, q, Uq);
            Ur = fmaf(u1, r, Ur); Us = fmaf(u1, ss, Us);
            Vp = fmaf(u2, p, Vp); Vq = fmaf(u2, q, Vq);
            Vr = fmaf(u2, r, Vr); Vs = fmaf(u2, ss, Vs);
        }
    }

    float m0  = m0x + ct * (A + Dd) + st * (B - Cc);
    float r1r = c2t * Ur + s2t * Vr;   // r1 . r
    float r2s = s2t * Us - c2t * Vs;   // r2 . s
    float r2r = s2t * Ur - c2t * Vr;   // r2 . r
    float r1s = c2t * Us + s2t * Vs;   // r1 . s
    float mv1 = sa * ct - sb * st + Up - Vq + r1r - r2s;
    float mv2 = sa * st + sb * ct + Vp + Uq + r2r + r1s;

    atomicAdd(&g_scratch[d],            1.0f);
    atomicAdd(&g_scratch[VMAX + d],     m0);
    atomicAdd(&g_scratch[2 * VMAX + d], mv1);
    atomicAdd(&g_scratch[3 * VMAX + d], mv2);
}

// Per-vertex finalize: normalize by degree, self-connections, sigmoid gate, frame projection.
__global__ __launch_bounds__(256) void vertex_kernel(
    const float* __restrict__ x,
    const float* __restrict__ e1,
    const float* __restrict__ e2,
    const float* __restrict__ w_self0,
    const float* __restrict__ w_self11,
    float* __restrict__ out,
    int V)
{
    __shared__ float sw[48];   // [0:16) w_self0, [16:48) w_self11 (k*2+c)
    int t = threadIdx.x;
    if (t < 16)       sw[t] = w_self0[t];
    else if (t < 48)  sw[t] = w_self11[t - 16];
    __syncthreads();

    int v = blockIdx.x * blockDim.x + t;
    if (v >= V) return;

    float deg   = g_scratch[v];
    float inv   = 1.0f / fmaxf(deg, 1.0f);
    float mag   = g_scratch[VMAX + v] * inv;
    float agg1  = g_scratch[2 * VMAX + v] * inv;
    float agg2  = g_scratch[3 * VMAX + v] * inv;

    const float4* xr = (const float4*)(x + (long long)v * 48);
    float selfdot = 0.f;
#pragma unroll
    for (int i = 0; i < 4; i++) {
        float4 vv = __ldg(&xr[i]);
        selfdot = fmaf(vv.x, sw[i * 4 + 0],
                  fmaf(vv.y, sw[i * 4 + 1],
                  fmaf(vv.z, sw[i * 4 + 2],
                  fmaf(vv.w, sw[i * 4 + 3], selfdot))));
    }
    mag += selfdot;

    float t1 = agg1, t2 = agg2;
#pragma unroll
    for (int i = 0; i < 8; i++) {
        float4 vv = __ldg(&xr[4 + i]);
        int k = 2 * i;
        float sa0 = sw[16 + 2 * k],     sb0 = sw[16 + 2 * k + 1];
        float sa1 = sw[16 + 2 * k + 2], sb1 = sw[16 + 2 * k + 3];
        // t1 += x1[k,0]*sa - x1[k,1]*sb ; t2 += x1[k,1]*sa + x1[k,0]*sb
        t1 += vv.x * sa0 - vv.y * sb0 + vv.z * sa1 - vv.w * sb1;
        t2 += vv.y * sa0 + vv.x * sb0 + vv.w * sa1 + vv.z * sb1;
    }

    float ms = 2.0f / (1.0f + __expf(-mag));

    float a1 = e1[v * 3 + 0], a2 = e1[v * 3 + 1], a3 = e1[v * 3 + 2];
    float b1 = e2[v * 3 + 0], b2 = e2[v * 3 + 1], b3 = e2[v * 3 + 2];
    out[v * 3 + 0] = (t1 * a1 + t2 * b1) * ms;
    out[v * 3 + 1] = (t1 * a2 + t2 * b2) * ms;
    out[v * 3 + 2] = (t1 * a3 + t2 * b3) * ms;
}

extern "C" void kernel_launch(void* const* d_in, const int* in_sizes, int n_in,
                              void* d_out, int out_size) {
    const float* x            = (const float*)d_in[0];
    const int*   ei           = (const int*)d_in[1];
    const float* angles       = (const float*)d_in[2];
    const float* transporters = (const float*)d_in[3];
    const float* e1           = (const float*)d_in[4];
    const float* e2           = (const float*)d_in[5];
    const float* w_self0      = (const float*)d_in[6];
    const float* w_n00        = (const float*)d_in[7];
    const float* w_n10        = (const float*)d_in[8];
    const float* w_self11     = (const float*)d_in[9];
    const float* w_n01        = (const float*)d_in[10];
    const float* w_n11        = (const float*)d_in[11];
    float* out = (float*)d_out;

    int E = in_sizes[2];          // angles count
    int V = in_sizes[4] / 3;      // e1 is (V,3)

    zero_kernel<<<(4 * V + 255) / 256, 256>>>(4 * V);
    edge_kernel<<<(E + 255) / 256, 256>>>(x, ei, angles, transporters,
                                          w_n00, w_n10, w_n01, w_n11, E);
    vertex_kernel<<<(V + 255) / 256, 256>>>(x, e1, e2, w_self0, w_self11, out, V);
}

// round 5
// speedup vs baseline: 1.1687x; 1.1687x over previous
#include <cuda_runtime.h>

// Problem constants: V=100000, C0=16, C1=16, E=1600000
#define VMAX 100000
#define EPB  128     // edges per block (== block size for edge kernel)

// Scratch per vertex: {deg, m0, mv1, mv2}
__device__ float4 g_scratch4[VMAX];

__global__ __launch_bounds__(256) void zero_kernel(int n4) {
    int i = blockIdx.x * blockDim.x + threadIdx.x;
    if (i < n4) ((float*)g_scratch4)[i] = 0.0f;
}

// Per-edge message computation.
// SMEM weight layout: [0:16) w_n00, [16:48) w_n10 (k*2+c), [48:80) w_n01 (k*2+c), [80:144) w_n11 (k*4+c)
__global__ __launch_bounds__(EPB) void edge_kernel(
    const float* __restrict__ x,
    const int* __restrict__ ei,             // [2, E] int32: src then dst
    const float* __restrict__ angles,
    const float* __restrict__ transporters,
    const float* __restrict__ w_n00,
    const float* __restrict__ w_n10,
    const float* __restrict__ w_n01,
    const float* __restrict__ w_n11,
    int E)
{
    __shared__ float sw[144];
    __shared__ int   s_src[EPB];
    __shared__ float sx[EPB][49];           // stride 49: conflict-free compute reads

    int t = threadIdx.x;
    for (int i = t; i < 144; i += EPB) {
        float w;
        if (i < 16)       w = w_n00[i];
        else if (i < 48)  w = w_n10[i - 16];
        else if (i < 80)  w = w_n01[i - 48];
        else              w = w_n11[i - 80];
        sw[i] = w;
    }

    int e0 = blockIdx.x * EPB;
    int e  = e0 + t;
    if (e < E) s_src[t] = ei[e];
    __syncthreads();

    // Cooperative coalesced gather: 12 consecutive threads stream one 192B row.
    #pragma unroll
    for (int it = 0; it < 12; it++) {
        int idx = it * EPB + t;             // [0, EPB*12)
        int row = idx / 12;
        int seg = idx - row * 12;
        if (e0 + row < E) {
            float4 v = __ldg((const float4*)(x + (long long)s_src[row] * 48) + seg);
            float* dp = &sx[row][seg * 4];
            dp[0] = v.x; dp[1] = v.y; dp[2] = v.z; dp[3] = v.w;
        }
    }
    __syncthreads();

    if (e >= E) return;

    int d = ei[E + e];

    float sg, cg; __sincosf(transporters[e], &sg, &cg);
    float st, ct; __sincosf(angles[e],       &st, &ct);
    float c2t = ct * ct - st * st;
    float s2t = 2.0f * st * ct;

    const float* xr = sx[t];

    // x0 dot products: m0x = x0.w_n00, sa = x0.w_n01[:,0], sb = x0.w_n01[:,1]
    float m0x = 0.f, sa = 0.f, sb = 0.f;
#pragma unroll
    for (int k = 0; k < 16; k++) {
        float v = xr[k];
        m0x = fmaf(v, sw[k],              m0x);
        sa  = fmaf(v, sw[48 + 2 * k],     sa);
        sb  = fmaf(v, sw[48 + 2 * k + 1], sb);
    }

    // x1 part: rotate by transporter, then 12 dot products
    float A = 0.f, B = 0.f, Cc = 0.f, Dd = 0.f;
    float Up = 0.f, Uq = 0.f, Ur = 0.f, Us = 0.f;
    float Vp = 0.f, Vq = 0.f, Vr = 0.f, Vs = 0.f;
#pragma unroll
    for (int k = 0; k < 16; k++) {
        float a1 = xr[16 + 2 * k];
        float b1 = xr[17 + 2 * k];
        float u1 = cg * a1 - sg * b1;
        float u2 = sg * a1 + cg * b1;
        float wa = sw[16 + 2 * k], wb = sw[16 + 2 * k + 1];
        A  = fmaf(u1, wa, A);  B  = fmaf(u2, wa, B);
        Cc = fmaf(u1, wb, Cc); Dd = fmaf(u2, wb, Dd);
        float p = sw[80 + 4 * k],     q  = sw[80 + 4 * k + 1];
        float r = sw[80 + 4 * k + 2], ss = sw[80 + 4 * k + 3];
        Up = fmaf(u1, p, Up); Uq = fmaf(u1, q, Uq);
        Ur = fmaf(u1, r, Ur); Us = fmaf(u1, ss, Us);
        Vp = fmaf(u2, p, Vp); Vq = fmaf(u2, q, Vq);
        Vr = fmaf(u2, r, Vr); Vs = fmaf(u2, ss, Vs);
    }

    float m0  = m0x + ct * (A + Dd) + st * (B - Cc);
    float r1r = c2t * Ur + s2t * Vr;   // r1 . r
    float r2s = s2t * Us - c2t * Vs;   // r2 . s
    float r2r = s2t * Ur - c2t * Vr;   // r2 . r
    float r1s = c2t * Us + s2t * Vs;   // r1 . s
    float mv1 = sa * ct - sb * st + Up - Vq + r1r - r2s;
    float mv2 = sa * st + sb * ct + Vp + Uq + r2r + r1s;

    // Single vectorized 16B reduction: {deg, m0, mv1, mv2}
    float4* dst = &g_scratch4[d];
    asm volatile("red.global.add.v4.f32 [%0], {%1, %2, %3, %4};"
                 :: "l"(dst), "f"(1.0f), "f"(m0), "f"(mv1), "f"(mv2)
                 : "memory");
}

// Per-vertex finalize: normalize by degree, self-connections, sigmoid gate, frame projection.
__global__ __launch_bounds__(256) void vertex_kernel(
    const float* __restrict__ x,
    const float* __restrict__ e1,
    const float* __restrict__ e2,
    const float* __restrict__ w_self0,
    const float* __restrict__ w_self11,
    float* __restrict__ out,
    int V)
{
    __shared__ float sw[48];   // [0:16) w_self0, [16:48) w_self11 (k*2+c)
    int t = threadIdx.x;
    if (t < 16)       sw[t] = w_self0[t];
    else if (t < 48)  sw[t] = w_self11[t - 16];
    __syncthreads();

    int v = blockIdx.x * blockDim.x + t;
    if (v >= V) return;

    float4 sc  = g_scratch4[v];
    float inv  = 1.0f / fmaxf(sc.x, 1.0f);
    float mag  = sc.y * inv;
    float agg1 = sc.z * inv;
    float agg2 = sc.w * inv;

    const float4* xr = (const float4*)(x + (long long)v * 48);
    float selfdot = 0.f;
#pragma unroll
    for (int i = 0; i < 4; i++) {
        float4 vv = __ldg(&xr[i]);
        selfdot = fmaf(vv.x, sw[i * 4 + 0],
                  fmaf(vv.y, sw[i * 4 + 1],
                  fmaf(vv.z, sw[i * 4 + 2],
                  fmaf(vv.w, sw[i * 4 + 3], selfdot))));
    }
    mag += selfdot;

    float t1 = agg1, t2 = agg2;
#pragma unroll
    for (int i = 0; i < 8; i++) {
        float4 vv = __ldg(&xr[4 + i]);
        int k = 2 * i;
        float sa0 = sw[16 + 2 * k],     sb0 = sw[16 + 2 * k + 1];
        float sa1 = sw[16 + 2 * k + 2], sb1 = sw[16 + 2 * k + 3];
        t1 += vv.x * sa0 - vv.y * sb0 + vv.z * sa1 - vv.w * sb1;
        t2 += vv.y * sa0 + vv.x * sb0 + vv.w * sa1 + vv.z * sb1;
    }

    float ms = 2.0f / (1.0f + __expf(-mag));

    float a1 = e1[v * 3 + 0], a2 = e1[v * 3 + 1], a3 = e1[v * 3 + 2];
    float b1 = e2[v * 3 + 0], b2 = e2[v * 3 + 1], b3 = e2[v * 3 + 2];
    out[v * 3 + 0] = (t1 * a1 + t2 * b1) * ms;
    out[v * 3 + 1] = (t1 * a2 + t2 * b2) * ms;
    out[v * 3 + 2] = (t1 * a3 + t2 * b3) * ms;
}

extern "C" void kernel_launch(void* const* d_in, const int* in_sizes, int n_in,
                              void* d_out, int out_size) {
    const float* x            = (const float*)d_in[0];
    const int*   ei           = (const int*)d_in[1];
    const float* angles       = (const float*)d_in[2];
    const float* transporters = (const float*)d_in[3];
    const float* e1           = (const float*)d_in[4];
    const float* e2           = (const float*)d_in[5];
    const float* w_self0      = (const float*)d_in[6];
    const float* w_n00        = (const float*)d_in[7];
    const float* w_n10        = (const float*)d_in[8];
    const float* w_self11     = (const float*)d_in[9];
    const float* w_n01        = (const float*)d_in[10];
    const float* w_n11        = (const float*)d_in[11];
    float* out = (float*)d_out;

    int E = in_sizes[2];          // angles count
    int V = in_sizes[4] / 3;      // e1 is (V,3)

    zero_kernel<<<(4 * V + 255) / 256, 256>>>(4 * V);
    edge_kernel<<<(E + EPB - 1) / EPB, EPB>>>(x, ei, angles, transporters,
                                              w_n00, w_n10, w_n01, w_n11, E);
    vertex_kernel<<<(V + 255) / 256, 256>>>(x, e1, e2, w_self0, w_self11, out, V);
}